// round 7
// baseline (speedup 1.0000x reference)
#include <cuda_runtime.h>
#include <cuda_bf16.h>
#include <stdint.h>
#include <math.h>

// ---------------- dims ----------------
#define HD 512
#define BD 512
#define TD 128

#define MB 64        // batch rows per CTA (M)
#define NU 32        // units per CTA; N = 4 gates x 32 = 128
#define KC 64        // k per stage

// int8 smem stage layout: rows padded to 80B (64B data + 16 pad)
#define ROWB 80
#define OFF_A2 5120            // 64*80
#define OFF_W1 10240
#define OFF_W2 20480
#define STAGE_BYTES 30720      // 2*5120 + 2*10240
#define NSTG 4
#define OFF_XS (NSTG*STAGE_BYTES)          // 122880
#define SMEM_TOTAL (OFF_XS + 1024)

// fixed-point scales
#define C1 (1.0f/260096.0f)        // 1/(127*2048)
#define C2 (1.0f/66064384.0f)      // C1/254

// ---------------- persistent device state ----------------
__device__ float g_c1[BD*HD];
__device__ float g_c2[BD*HD];
__device__ float g_h2f[2][BD*HD];
__device__ __align__(16) int8_t g_h1q1[2][BD*HD], g_h1q2[2][BD*HD];
__device__ __align__(16) int8_t g_h2q1[2][BD*HD], g_h2q2[2][BD*HD];
__device__ float g_b0[4*HD], g_b1[4*HD];
__device__ __align__(16) int8_t g_whh0a[4*HD*HD], g_whh0b[4*HD*HD];
__device__ __align__(16) int8_t g_wih1a[4*HD*HD], g_wih1b[4*HD*HD];
__device__ __align__(16) int8_t g_whh1a[4*HD*HD], g_whh1b[4*HD*HD];

// ---------------- helpers ----------------
__device__ __forceinline__ uint32_t smem_u32(const void* p) {
    uint32_t a;
    asm("{ .reg .u64 t; cvta.to.shared.u64 t, %1; cvt.u32.u64 %0, t; }" : "=r"(a) : "l"(p));
    return a;
}
__device__ __forceinline__ void cpa16(uint32_t dst, const void* src) {
    asm volatile("cp.async.cg.shared.global [%0], [%1], 16;" :: "r"(dst), "l"(src));
}
#define CP_COMMIT() asm volatile("cp.async.commit_group;")
#define CP_WAIT(n)  asm volatile("cp.async.wait_group %0;" :: "n"(n))

__device__ __forceinline__ void ldm4(uint32_t (&r)[4], uint32_t addr) {
    asm volatile("ldmatrix.sync.aligned.m8n8.x4.shared.b16 {%0,%1,%2,%3}, [%4];"
        : "=r"(r[0]), "=r"(r[1]), "=r"(r[2]), "=r"(r[3]) : "r"(addr));
}
__device__ __forceinline__ void mma_s8(int (&d)[4], const uint32_t a[4], const uint32_t b[2]) {
    asm volatile("mma.sync.aligned.m16n8k32.row.col.s32.s8.s8.s32 "
        "{%0,%1,%2,%3}, {%4,%5,%6,%7}, {%8,%9}, {%0,%1,%2,%3};"
        : "+r"(d[0]), "+r"(d[1]), "+r"(d[2]), "+r"(d[3])
        : "r"(a[0]), "r"(a[1]), "r"(a[2]), "r"(a[3]), "r"(b[0]), "r"(b[1]));
}

__device__ __forceinline__ float sigf(float z) { return 1.0f / (1.0f + __expf(-z)); }
__device__ __forceinline__ float tanhsf(float z) {
    float e = __expf(2.0f * z);
    return 1.0f - 2.0f / (e + 1.0f);
}

// quantize h in (-1,1): a1 = rint(127h), a2 = rint(254*(127h - a1))
__device__ __forceinline__ void quanth(float h, int8_t& q1, int8_t& q2) {
    float hs = h * 127.0f;
    int a1 = __float2int_rn(hs);
    int a2 = __float2int_rn((hs - (float)a1) * 254.0f);
    q1 = (int8_t)a1; q2 = (int8_t)a2;
}

// ---------------- stage loader: A(q1,q2) 64xKC, W(w1,w2) 128xKC (int8) ----------------
__device__ __forceinline__ void stage_load(uint32_t st,
    const int8_t* __restrict__ a1, const int8_t* __restrict__ a2,
    const int8_t* __restrict__ w1, const int8_t* __restrict__ w2,
    int b0, int u0, int k0, int tid)
{
    {
        int r = tid >> 2, c = (tid & 3) * 16;
        size_t goff = (size_t)(b0 + r) * HD + k0 + c;
        uint32_t doff = (uint32_t)(r * ROWB + c);
        cpa16(st + doff,          a1 + goff);
        cpa16(st + OFF_A2 + doff, a2 + goff);
    }
    #pragma unroll
    for (int q = 0; q < 2; q++) {
        int i = tid + q * 256;
        int n = i >> 2, c = (i & 3) * 16;
        int wrow = ((n >> 5) << 9) + u0 + (n & 31);    // gate*512 + u
        size_t goff = (size_t)wrow * HD + k0 + c;
        uint32_t doff = (uint32_t)(n * ROWB + c);
        cpa16(st + OFF_W1 + doff, w1 + goff);
        cpa16(st + OFF_W2 + doff, w2 + goff);
    }
}

// ---------------- compute one 64-k stage: 3 int8 products ----------------
__device__ __forceinline__ void compute_stage(uint32_t sbase,
    int (&d1)[2][4][4], int (&d2)[2][4][4], int wm, int wn, int lane)
{
    const int l7 = lane & 7, grp = lane >> 3;
    const uint32_t a_row = (uint32_t)(((grp & 1) << 3) + l7);
    const uint32_t a_kb  = (uint32_t)((grp >> 1) << 4);
    const uint32_t b_n   = (uint32_t)(((grp >> 1) << 3) + l7);
    const uint32_t b_kb  = (uint32_t)((grp & 1) << 4);

    #pragma unroll
    for (int kk = 0; kk < 2; kk++) {
        uint32_t kb = kk * 32;   // 32 int8 per k-step = 32B
        uint32_t A1[2][4], A2[2][4], B1[2][4], B2[2][4];
        #pragma unroll
        for (int mi = 0; mi < 2; mi++) {
            uint32_t ra = sbase + (wm * 32 + mi * 16 + a_row) * ROWB + kb + a_kb;
            ldm4(A1[mi], ra);
            ldm4(A2[mi], ra + OFF_A2);
        }
        #pragma unroll
        for (int p = 0; p < 2; p++) {
            uint32_t rb = sbase + OFF_W1 + (wn * 32 + p * 16 + b_n) * ROWB + kb + b_kb;
            ldm4(B1[p], rb);
            ldm4(B2[p], rb + (OFF_W2 - OFF_W1));
        }
        #pragma unroll
        for (int mi = 0; mi < 2; mi++) {
            #pragma unroll
            for (int ni = 0; ni < 4; ni++) {
                const uint32_t* w1 = &B1[ni >> 1][(ni & 1) * 2];
                const uint32_t* w2 = &B2[ni >> 1][(ni & 1) * 2];
                mma_s8(d1[mi][ni], A1[mi], w1);   // a1*w1
                mma_s8(d2[mi][ni], A1[mi], w2);   // a1*w2
                mma_s8(d2[mi][ni], A2[mi], w1);   // a2*w1
            }
        }
    }
}

// ---------------- accum -> smem gate buffer (float, combined scales) ----------------
__device__ __forceinline__ void store_gbuf(float* gbuf,
    int (&d1)[2][4][4], int (&d2)[2][4][4], int wm, int wn, int lane)
{
    const int gid = lane >> 2, tig = lane & 3;
    #pragma unroll
    for (int mi = 0; mi < 2; mi++) {
        #pragma unroll
        for (int ni = 0; ni < 4; ni++) {
            int row = wm * 32 + mi * 16 + gid;
            int c0 = wn * 32 + ni * 8 + tig * 2;
            #pragma unroll
            for (int hh = 0; hh < 2; hh++) {
                gbuf[(row + hh * 8) * 132 + c0]     = C1 * (float)d1[mi][ni][hh*2]   + C2 * (float)d2[mi][ni][hh*2];
                gbuf[(row + hh * 8) * 132 + c0 + 1] = C1 * (float)d1[mi][ni][hh*2+1] + C2 * (float)d2[mi][ni][hh*2+1];
            }
        }
    }
}

// ---------------- setup kernels ----------------
__global__ void __launch_bounds__(256) zero_state() {
    int idx = blockIdx.x * 256 + threadIdx.x;   // grid 1024
    g_c1[idx] = 0.f; g_c2[idx] = 0.f;
    g_h1q1[0][idx] = 0; g_h1q2[0][idx] = 0;
    g_h2q1[0][idx] = 0; g_h2q2[0][idx] = 0;
}
__global__ void __launch_bounds__(256) prep_bias(
    const float* __restrict__ b_ih0, const float* __restrict__ b_hh0,
    const float* __restrict__ b_ih1, const float* __restrict__ b_hh1) {
    int j = blockIdx.x * 256 + threadIdx.x;     // grid 8
    g_b0[j] = b_ih0[j] + b_hh0[j];
    g_b1[j] = b_ih1[j] + b_hh1[j];
}
// w1 = rint(2048 w) (|.|<=91), w2 = rint(254*(2048w - w1))
__global__ void __launch_bounds__(256) quantw(const float* __restrict__ w, int which) {
    int8_t *p1, *p2;
    if (which == 0)      { p1 = g_whh0a; p2 = g_whh0b; }
    else if (which == 1) { p1 = g_wih1a; p2 = g_wih1b; }
    else                 { p1 = g_whh1a; p2 = g_whh1b; }
    int i = blockIdx.x * 256 + threadIdx.x;     // grid 4096
    float v = w[i] * 2048.0f;
    int q1 = __float2int_rn(v);
    int q2 = __float2int_rn((v - (float)q1) * 254.0f);
    p1[i] = (int8_t)q1; p2[i] = (int8_t)q2;
}

// ---------------- the pipelined GEMM mainloop ----------------
// NS stages of KC. For phaseB, arrays switch at stage 8 (segment 1).
template<int NS>
__device__ __forceinline__ void run_pipeline(
    char* sm, uint32_t sb,
    const int8_t* const* A1s, const int8_t* const* A2s,
    const int8_t* const* W1s, const int8_t* const* W2s,
    int b0, int u0, int tid,
    int (&d1)[2][4][4], int (&d2)[2][4][4], int wm, int wn, int lane)
{
    stage_load(sb, A1s[0], A2s[0], W1s[0], W2s[0], b0, u0, 0, tid);
    CP_COMMIT();
    {
        int sg = 1 >> 3;
        stage_load(sb + STAGE_BYTES, A1s[sg], A2s[sg], W1s[sg], W2s[sg],
                   b0, u0, (1 & 7) * KC, tid);
        CP_COMMIT();
    }
    #pragma unroll 1
    for (int i = 0; i < NS; i++) {
        if (i + 2 < NS) {
            int j = i + 2, sg = j >> 3;
            stage_load(sb + (j % NSTG) * STAGE_BYTES, A1s[sg], A2s[sg], W1s[sg], W2s[sg],
                       b0, u0, (j & 7) * KC, tid);
            CP_COMMIT();
            CP_WAIT(2);
        } else {
            CP_WAIT(0);
        }
        __syncthreads();
        compute_stage(sb + (i % NSTG) * STAGE_BYTES, d1, d2, wm, wn, lane);
    }
    __syncthreads();
}

// ---------------- phase A: layer-0 step ----------------
__global__ void __launch_bounds__(256) phaseA_k(
    int rd, const float* __restrict__ xin, int t, int y_from_c2,
    const float* __restrict__ w_lin, const float* __restrict__ b_lin,
    float* __restrict__ out, int t_out, const float* __restrict__ w_ih0)
{
    extern __shared__ char sm[];
    uint32_t sb = smem_u32(sm);
    const int tid = threadIdx.x, lane = tid & 31, wid = tid >> 5;
    const int wm = wid >> 2, wn = wid & 3;
    const int b0 = blockIdx.x * MB, u0 = blockIdx.y * NU;
    float* xs = (float*)(sm + OFF_XS);

    const int8_t* A1s[2] = { g_h1q1[rd], g_h1q1[rd] };
    const int8_t* A2s[2] = { g_h1q2[rd], g_h1q2[rd] };
    const int8_t* W1s[2] = { g_whh0a, g_whh0a };
    const int8_t* W2s[2] = { g_whh0b, g_whh0b };

    // input scalar per batch row
    if (xin != nullptr) {
        if (tid < MB) xs[tid] = xin[(size_t)(b0 + tid) * TD + t];
    } else {
        const float* ysrc = y_from_c2 ? g_c2 : g_h2f[rd];
        int rrow = tid >> 2, p = tid & 3;
        const float4* hr = (const float4*)(ysrc + (size_t)(b0 + rrow) * HD);
        const float4* wl = (const float4*)w_lin;
        float s = 0.f;
        #pragma unroll 8
        for (int kk = p; kk < HD / 4; kk += 4) {
            float4 a = hr[kk]; float4 w = wl[kk];
            s += a.x * w.x + a.y * w.y + a.z * w.z + a.w * w.w;
        }
        s += __shfl_xor_sync(0xffffffffu, s, 1);
        s += __shfl_xor_sync(0xffffffffu, s, 2);
        if (p == 0) {
            float yv = s + b_lin[0];
            xs[rrow] = yv;
            if (blockIdx.y == 0) out[(size_t)(b0 + rrow) * TD + t_out] = yv;
        }
    }

    int d1[2][4][4] = {}, d2[2][4][4] = {};
    run_pipeline<8>(sm, sb, A1s, A2s, W1s, W2s, b0, u0, tid, d1, d2, wm, wn, lane);

    float* gbuf = (float*)sm;
    store_gbuf(gbuf, d1, d2, wm, wn, lane);
    __syncthreads();

    // cell update: thread -> (row, 8 consecutive u)
    {
        int row = tid >> 2, ub = (tid & 3) * 8;
        float xi = xs[row];
        size_t rowbase = (size_t)(b0 + row) * HD + u0 + ub;
        float4 ca = *(const float4*)(g_c1 + rowbase);
        float4 cb = *(const float4*)(g_c1 + rowbase + 4);
        float cv[8] = {ca.x, ca.y, ca.z, ca.w, cb.x, cb.y, cb.z, cb.w};
        __align__(8) int8_t q1[8], q2[8];
        #pragma unroll
        for (int j = 0; j < 8; j++) {
            int ul = ub + j, ug = u0 + ul;
            float iv = gbuf[row * 132 + ul]      + g_b0[ug]        + xi * w_ih0[ug];
            float fv = gbuf[row * 132 + 32 + ul] + g_b0[HD + ug]   + xi * w_ih0[HD + ug];
            float gv = gbuf[row * 132 + 64 + ul] + g_b0[2*HD + ug] + xi * w_ih0[2*HD + ug];
            float ov = gbuf[row * 132 + 96 + ul] + g_b0[3*HD + ug] + xi * w_ih0[3*HD + ug];
            float cn = sigf(fv) * cv[j] + sigf(iv) * tanhsf(gv);
            cv[j] = cn;
            float h = sigf(ov) * tanhsf(cn);
            quanth(h, q1[j], q2[j]);
        }
        *(float4*)(g_c1 + rowbase)     = make_float4(cv[0], cv[1], cv[2], cv[3]);
        *(float4*)(g_c1 + rowbase + 4) = make_float4(cv[4], cv[5], cv[6], cv[7]);
        *(uint2*)(g_h1q1[rd ^ 1] + rowbase) = *(const uint2*)q1;
        *(uint2*)(g_h1q2[rd ^ 1] + rowbase) = *(const uint2*)q2;
    }
}

// ---------------- phase B: layer-1 step (K=1024, two segments) ----------------
__global__ void __launch_bounds__(256) phaseB_k(int rd)
{
    extern __shared__ char sm[];
    uint32_t sb = smem_u32(sm);
    const int tid = threadIdx.x, lane = tid & 31, wid = tid >> 5;
    const int wm = wid >> 2, wn = wid & 3;
    const int b0 = blockIdx.x * MB, u0 = blockIdx.y * NU;

    const int8_t* A1s[2] = { g_h1q1[rd ^ 1], g_h2q1[rd] };
    const int8_t* A2s[2] = { g_h1q2[rd ^ 1], g_h2q2[rd] };
    const int8_t* W1s[2] = { g_wih1a, g_whh1a };
    const int8_t* W2s[2] = { g_wih1b, g_whh1b };

    int d1[2][4][4] = {}, d2[2][4][4] = {};
    run_pipeline<16>(sm, sb, A1s, A2s, W1s, W2s, b0, u0, tid, d1, d2, wm, wn, lane);

    float* gbuf = (float*)sm;
    store_gbuf(gbuf, d1, d2, wm, wn, lane);
    __syncthreads();

    {
        int row = tid >> 2, ub = (tid & 3) * 8;
        size_t rowbase = (size_t)(b0 + row) * HD + u0 + ub;
        float4 ca = *(const float4*)(g_c2 + rowbase);
        float4 cb = *(const float4*)(g_c2 + rowbase + 4);
        float cv[8] = {ca.x, ca.y, ca.z, ca.w, cb.x, cb.y, cb.z, cb.w};
        float hv[8];
        __align__(8) int8_t q1[8], q2[8];
        #pragma unroll
        for (int j = 0; j < 8; j++) {
            int ul = ub + j, ug = u0 + ul;
            float iv = gbuf[row * 132 + ul]      + g_b1[ug];
            float fv = gbuf[row * 132 + 32 + ul] + g_b1[HD + ug];
            float gv = gbuf[row * 132 + 64 + ul] + g_b1[2*HD + ug];
            float ov = gbuf[row * 132 + 96 + ul] + g_b1[3*HD + ug];
            float cn = sigf(fv) * cv[j] + sigf(iv) * tanhsf(gv);
            cv[j] = cn;
            float h = sigf(ov) * tanhsf(cn);
            hv[j] = h;
            quanth(h, q1[j], q2[j]);
        }
        *(float4*)(g_c2 + rowbase)     = make_float4(cv[0], cv[1], cv[2], cv[3]);
        *(float4*)(g_c2 + rowbase + 4) = make_float4(cv[4], cv[5], cv[6], cv[7]);
        *(float4*)(g_h2f[rd ^ 1] + rowbase)     = make_float4(hv[0], hv[1], hv[2], hv[3]);
        *(float4*)(g_h2f[rd ^ 1] + rowbase + 4) = make_float4(hv[4], hv[5], hv[6], hv[7]);
        *(uint2*)(g_h2q1[rd ^ 1] + rowbase) = *(const uint2*)q1;
        *(uint2*)(g_h2q2[rd ^ 1] + rowbase) = *(const uint2*)q2;
    }
}

// ---------------- final prediction ----------------
__global__ void __launch_bounds__(256) final_y(
    int rd, const float* __restrict__ w_lin, const float* __restrict__ b_lin,
    float* __restrict__ out)
{
    int tid = threadIdx.x;
    int rrow = blockIdx.x * 128 + (tid >> 1);   // grid 4
    int p = tid & 1;
    const float4* hr = (const float4*)(g_h2f[rd] + (size_t)rrow * HD);
    const float4* wl = (const float4*)w_lin;
    float s = 0.f;
    #pragma unroll 16
    for (int kk = p; kk < HD / 4; kk += 2) {
        float4 a = hr[kk]; float4 w = wl[kk];
        s += a.x * w.x + a.y * w.y + a.z * w.z + a.w * w.w;
    }
    s += __shfl_xor_sync(0xffffffffu, s, 1);
    if (p == 0) out[(size_t)rrow * TD + (TD - 1)] = s + b_lin[0];
}

// ---------------- host launcher ----------------
extern "C" void kernel_launch(void* const* d_in, const int* in_sizes, int n_in,
                              void* d_out, int out_size)
{
    const float* x     = (const float*)d_in[0];
    const float* w_ih0 = (const float*)d_in[3];
    const float* w_hh0 = (const float*)d_in[4];
    const float* b_ih0 = (const float*)d_in[5];
    const float* b_hh0 = (const float*)d_in[6];
    const float* w_ih1 = (const float*)d_in[7];
    const float* w_hh1 = (const float*)d_in[8];
    const float* b_ih1 = (const float*)d_in[9];
    const float* b_hh1 = (const float*)d_in[10];
    const float* w_lin = (const float*)d_in[11];
    const float* b_lin = (const float*)d_in[12];
    float* out = (float*)d_out;

    cudaFuncSetAttribute(phaseA_k, cudaFuncAttributeMaxDynamicSharedMemorySize, SMEM_TOTAL);
    cudaFuncSetAttribute(phaseB_k, cudaFuncAttributeMaxDynamicSharedMemorySize, SMEM_TOTAL);

    zero_state<<<1024, 256>>>();
    prep_bias<<<8, 256>>>(b_ih0, b_hh0, b_ih1, b_hh1);
    quantw<<<4096, 256>>>(w_hh0, 0);
    quantw<<<4096, 256>>>(w_ih1, 1);
    quantw<<<4096, 256>>>(w_hh1, 2);

    dim3 grid(BD / MB, HD / NU);   // (8, 16) = 128 CTAs
    int s = 0;
    for (int t = 0; t < TD; ++t, ++s) {
        phaseA_k<<<grid, 256, SMEM_TOTAL>>>(s & 1, x, t, 0,
                                            nullptr, nullptr, nullptr, 0, w_ih0);
        phaseB_k<<<grid, 256, SMEM_TOTAL>>>(s & 1);
    }
    for (int i = 1; i < TD; ++i, ++s) {
        phaseA_k<<<grid, 256, SMEM_TOTAL>>>(s & 1, nullptr, 0, (i == 1) ? 1 : 0,
                                            w_lin, b_lin, out, i - 1, w_ih0);
        phaseB_k<<<grid, 256, SMEM_TOTAL>>>(s & 1);
    }
    final_y<<<4, 256>>>(s & 1, w_lin, b_lin, out);
}

// round 11
// speedup vs baseline: 2.0821x; 2.0821x over previous
#include <cuda_runtime.h>
#include <cuda_bf16.h>
#include <stdint.h>
#include <math.h>

// ---------------- dims ----------------
#define HD 512
#define BD 512
#define TD 128

#define MB 64        // batch rows per CTA (M)
#define NU 32        // units per CTA; N = 4 gates x 32 = 128
#define KC 64        // k per stage

// smem stage layout (bytes), rows padded to 144B (64 k bf16 = 128B data + 16B pad)
#define ROWB 144
#define A_BYTES (64 * ROWB)        // 9216
#define W_BYTES (128 * ROWB)       // 18432
#define OFF_ALO A_BYTES
#define OFF_WHI (2 * A_BYTES)
#define OFF_WLO (2 * A_BYTES + W_BYTES)
#define STAGE_BYTES (2 * A_BYTES + 2 * W_BYTES)   // 55296
#define NSTG 4
#define OFF_XS (NSTG * STAGE_BYTES)               // 221184
#define SMEM_TOTAL (OFF_XS + 1024)                // 222208

// ---------------- persistent device state ----------------
__device__ float g_c1[BD*HD];
__device__ float g_c2[BD*HD];
__device__ float g_h2f[2][BD*HD];
__device__ __align__(16) __nv_bfloat16 g_h1hi[2][BD*HD], g_h1lo[2][BD*HD];
__device__ __align__(16) __nv_bfloat16 g_h2hi[2][BD*HD], g_h2lo[2][BD*HD];
__device__ float g_b0[4*HD], g_b1[4*HD];
__device__ __align__(16) __nv_bfloat16 g_whh0hi[4*HD*HD], g_whh0lo[4*HD*HD];
__device__ __align__(16) __nv_bfloat16 g_wih1hi[4*HD*HD], g_wih1lo[4*HD*HD];
__device__ __align__(16) __nv_bfloat16 g_whh1hi[4*HD*HD], g_whh1lo[4*HD*HD];

// ---------------- helpers ----------------
__device__ __forceinline__ uint32_t smem_u32(const void* p) {
    uint32_t a;
    asm("{ .reg .u64 t; cvta.to.shared.u64 t, %1; cvt.u32.u64 %0, t; }" : "=r"(a) : "l"(p));
    return a;
}
__device__ __forceinline__ void cpa16(uint32_t dst, const void* src) {
    asm volatile("cp.async.cg.shared.global [%0], [%1], 16;" :: "r"(dst), "l"(src));
}
#define CP_COMMIT() asm volatile("cp.async.commit_group;")
#define CP_WAIT(n)  asm volatile("cp.async.wait_group %0;" :: "n"(n))

__device__ __forceinline__ void ldm4(uint32_t (&r)[4], uint32_t addr) {
    asm volatile("ldmatrix.sync.aligned.m8n8.x4.shared.b16 {%0,%1,%2,%3}, [%4];"
        : "=r"(r[0]), "=r"(r[1]), "=r"(r[2]), "=r"(r[3]) : "r"(addr));
}
__device__ __forceinline__ void mma16816(float (&d)[4], const uint32_t a[4], const uint32_t b[2]) {
    asm volatile("mma.sync.aligned.m16n8k16.row.col.f32.bf16.bf16.f32 "
        "{%0,%1,%2,%3}, {%4,%5,%6,%7}, {%8,%9}, {%0,%1,%2,%3};"
        : "+f"(d[0]), "+f"(d[1]), "+f"(d[2]), "+f"(d[3])
        : "r"(a[0]), "r"(a[1]), "r"(a[2]), "r"(a[3]), "r"(b[0]), "r"(b[1]));
}

__device__ __forceinline__ float sigf(float z) { return 1.0f / (1.0f + __expf(-z)); }
__device__ __forceinline__ float tanhsf(float z) {
    float e = __expf(2.0f * z);
    return 1.0f - 2.0f / (e + 1.0f);
}

// ---------------- stage loader: A(hi,lo) 64xKC, W(hi,lo) 128xKC ----------------
__device__ __forceinline__ void stage_load(uint32_t st,
    const __nv_bfloat16* __restrict__ ahi, const __nv_bfloat16* __restrict__ alo,
    const __nv_bfloat16* __restrict__ whi, const __nv_bfloat16* __restrict__ wlo,
    int b0, int u0, int k0, int tid)
{
    #pragma unroll
    for (int q = 0; q < 2; q++) {
        int i = tid + q * 256;
        int r = i >> 3, s = (i & 7) * 8;           // s in bf16 elems (16B chunks)
        uint32_t doff = (uint32_t)(r * ROWB + s * 2);
        size_t goff = (size_t)(b0 + r) * HD + k0 + s;
        cpa16(st + doff,            ahi + goff);
        cpa16(st + OFF_ALO + doff,  alo + goff);
    }
    #pragma unroll
    for (int q = 0; q < 4; q++) {
        int i = tid + q * 256;
        int n = i >> 3, s = (i & 7) * 8;
        int wrow = ((n >> 5) << 9) + u0 + (n & 31);  // gate*512 + u
        uint32_t doff = (uint32_t)(n * ROWB + s * 2);
        size_t goff = (size_t)wrow * HD + k0 + s;
        cpa16(st + OFF_WHI + doff, whi + goff);
        cpa16(st + OFF_WLO + doff, wlo + goff);
    }
}

// ---------------- compute one 64-k stage: 3 products into d ----------------
__device__ __forceinline__ void compute_stage(uint32_t sbase, float (&d)[2][4][4],
                                              int wm, int wn, int lane)
{
    const int l7 = lane & 7, grp = lane >> 3;
    const uint32_t a_row = (uint32_t)(((grp & 1) << 3) + l7);
    const uint32_t a_kb  = (uint32_t)((grp >> 1) << 4);
    const uint32_t b_n   = (uint32_t)(((grp >> 1) << 3) + l7);
    const uint32_t b_kb  = (uint32_t)((grp & 1) << 4);

    #pragma unroll
    for (int kk = 0; kk < 4; kk++) {
        uint32_t kb = kk * 32;   // bytes: k16 step = 32B
        uint32_t Ah[2][4], Al[2][4], Bh[2][4], Bl[2][4];
        #pragma unroll
        for (int mi = 0; mi < 2; mi++) {
            uint32_t ra = sbase + (wm * 32 + mi * 16 + a_row) * ROWB + kb + a_kb;
            ldm4(Ah[mi], ra);
            ldm4(Al[mi], ra + OFF_ALO);
        }
        #pragma unroll
        for (int p = 0; p < 2; p++) {
            uint32_t rb = sbase + OFF_WHI + (wn * 32 + p * 16 + b_n) * ROWB + kb + b_kb;
            ldm4(Bh[p], rb);
            ldm4(Bl[p], rb + W_BYTES);
        }
        #pragma unroll
        for (int mi = 0; mi < 2; mi++) {
            #pragma unroll
            for (int ni = 0; ni < 4; ni++) {
                const uint32_t* bh = &Bh[ni >> 1][(ni & 1) * 2];
                const uint32_t* bl = &Bl[ni >> 1][(ni & 1) * 2];
                mma16816(d[mi][ni], Ah[mi], bh);
                mma16816(d[mi][ni], Al[mi], bh);
                mma16816(d[mi][ni], Ah[mi], bl);
            }
        }
    }
}

// ---------------- accum -> smem gate buffer ----------------
__device__ __forceinline__ void store_gbuf(float* gbuf, float (&d)[2][4][4],
                                           int wm, int wn, int lane)
{
    const int gid = lane >> 2, tig = lane & 3;
    #pragma unroll
    for (int mi = 0; mi < 2; mi++) {
        #pragma unroll
        for (int ni = 0; ni < 4; ni++) {
            int row = wm * 32 + mi * 16 + gid;
            int c0 = wn * 32 + ni * 8 + tig * 2;
            gbuf[row * 132 + c0]           = d[mi][ni][0];
            gbuf[row * 132 + c0 + 1]       = d[mi][ni][1];
            gbuf[(row + 8) * 132 + c0]     = d[mi][ni][2];
            gbuf[(row + 8) * 132 + c0 + 1] = d[mi][ni][3];
        }
    }
}

// ---------------- 4-stage ring pipeline, one sync per stage ----------------
template<int NS>
__device__ __forceinline__ void run_pipeline(
    uint32_t sb,
    const __nv_bfloat16* const* AHs, const __nv_bfloat16* const* ALs,
    const __nv_bfloat16* const* WHs, const __nv_bfloat16* const* WLs,
    int b0, int u0, int tid,
    float (&d)[2][4][4], int wm, int wn, int lane)
{
    // stages 0,1 already preloaded by caller
    #pragma unroll 1
    for (int i = 0; i < NS; i++) {
        if (i + 2 < NS) {
            int j = i + 2, sg = j >> 3;
            stage_load(sb + (j % NSTG) * STAGE_BYTES, AHs[sg], ALs[sg], WHs[sg], WLs[sg],
                       b0, u0, (j & 7) * KC, tid);
            CP_COMMIT();
            CP_WAIT(2);
        } else {
            CP_WAIT(0);
        }
        __syncthreads();
        compute_stage(sb + (i % NSTG) * STAGE_BYTES, d, wm, wn, lane);
    }
    __syncthreads();   // protect gbuf aliasing of stage slots
}

// ---------------- setup kernels ----------------
__global__ void __launch_bounds__(256) zero_state() {
    int idx = blockIdx.x * 256 + threadIdx.x;   // grid 1024
    g_c1[idx] = 0.f; g_c2[idx] = 0.f;
    __nv_bfloat16 z = __float2bfloat16(0.f);
    g_h1hi[0][idx] = z; g_h1lo[0][idx] = z;
    g_h2hi[0][idx] = z; g_h2lo[0][idx] = z;
}
__global__ void __launch_bounds__(256) prep_bias(
    const float* __restrict__ b_ih0, const float* __restrict__ b_hh0,
    const float* __restrict__ b_ih1, const float* __restrict__ b_hh1) {
    int j = blockIdx.x * 256 + threadIdx.x;     // grid 8
    g_b0[j] = b_ih0[j] + b_hh0[j];
    g_b1[j] = b_ih1[j] + b_hh1[j];
}
__global__ void __launch_bounds__(256) splitw(const float* __restrict__ w, int which) {
    __nv_bfloat16 *hi, *lo;
    if (which == 0)      { hi = g_whh0hi; lo = g_whh0lo; }
    else if (which == 1) { hi = g_wih1hi; lo = g_wih1lo; }
    else                 { hi = g_whh1hi; lo = g_whh1lo; }
    int i = blockIdx.x * 256 + threadIdx.x;     // grid 4096
    float v = w[i];
    __nv_bfloat16 h = __float2bfloat16(v);
    hi[i] = h;
    lo[i] = __float2bfloat16(v - __bfloat162float(h));
}

// ---------------- phase A: layer-0 step ----------------
__global__ void __launch_bounds__(256) phaseA_k(
    int rd, const float* __restrict__ xin, int t, int y_from_c2,
    const float* __restrict__ w_lin, const float* __restrict__ b_lin,
    float* __restrict__ out, int t_out, const float* __restrict__ w_ih0)
{
    extern __shared__ char sm[];
    uint32_t sb = smem_u32(sm);
    const int tid = threadIdx.x, lane = tid & 31, wid = tid >> 5;
    const int wm = wid >> 2, wn = wid & 3;
    const int b0 = blockIdx.x * MB, u0 = blockIdx.y * NU;
    float* xs = (float*)(sm + OFF_XS);

    const __nv_bfloat16* AHs[2] = { g_h1hi[rd], g_h1hi[rd] };
    const __nv_bfloat16* ALs[2] = { g_h1lo[rd], g_h1lo[rd] };
    const __nv_bfloat16* WHs[2] = { g_whh0hi, g_whh0hi };
    const __nv_bfloat16* WLs[2] = { g_whh0lo, g_whh0lo };

    // kick off pipeline fill FIRST so y/x work overlaps the loads
    stage_load(sb, AHs[0], ALs[0], WHs[0], WLs[0], b0, u0, 0, tid);
    CP_COMMIT();
    stage_load(sb + STAGE_BYTES, AHs[0], ALs[0], WHs[0], WLs[0], b0, u0, KC, tid);
    CP_COMMIT();

    // input scalar per batch row (teacher-forced or autoregressive)
    if (xin != nullptr) {
        if (tid < MB) xs[tid] = xin[(size_t)(b0 + tid) * TD + t];
    } else {
        const float* ysrc = y_from_c2 ? g_c2 : g_h2f[rd];
        int rrow = tid >> 2, p = tid & 3;
        const float4* hr = (const float4*)(ysrc + (size_t)(b0 + rrow) * HD);
        const float4* wl = (const float4*)w_lin;
        float s = 0.f;
        #pragma unroll 8
        for (int kk = p; kk < HD / 4; kk += 4) {
            float4 a = hr[kk]; float4 w = wl[kk];
            s += a.x * w.x + a.y * w.y + a.z * w.z + a.w * w.w;
        }
        s += __shfl_xor_sync(0xffffffffu, s, 1);
        s += __shfl_xor_sync(0xffffffffu, s, 2);
        if (p == 0) {
            float yv = s + b_lin[0];
            xs[rrow] = yv;
            if (blockIdx.y == 0) out[(size_t)(b0 + rrow) * TD + t_out] = yv;
        }
    }

    float d[2][4][4] = {};
    run_pipeline<8>(sb, AHs, ALs, WHs, WLs, b0, u0, tid, d, wm, wn, lane);

    float* gbuf = (float*)sm;
    store_gbuf(gbuf, d, wm, wn, lane);
    __syncthreads();

    // cell update: thread -> (row, 8 consecutive u)
    {
        int row = tid >> 2, ub = (tid & 3) * 8;
        float xi = xs[row];
        size_t rowbase = (size_t)(b0 + row) * HD + u0 + ub;
        float4 ca = *(const float4*)(g_c1 + rowbase);
        float4 cb = *(const float4*)(g_c1 + rowbase + 4);
        float cv[8] = {ca.x, ca.y, ca.z, ca.w, cb.x, cb.y, cb.z, cb.w};
        __align__(16) __nv_bfloat16 hh[8], hl[8];
        #pragma unroll
        for (int j = 0; j < 8; j++) {
            int ul = ub + j;
            int ug = u0 + ul;
            float iv = gbuf[row * 132 + ul]       + g_b0[ug]          + xi * w_ih0[ug];
            float fv = gbuf[row * 132 + 32 + ul]  + g_b0[HD + ug]     + xi * w_ih0[HD + ug];
            float gv = gbuf[row * 132 + 64 + ul]  + g_b0[2*HD + ug]   + xi * w_ih0[2*HD + ug];
            float ov = gbuf[row * 132 + 96 + ul]  + g_b0[3*HD + ug]   + xi * w_ih0[3*HD + ug];
            float cn = sigf(fv) * cv[j] + sigf(iv) * tanhsf(gv);
            cv[j] = cn;
            float h = sigf(ov) * tanhsf(cn);
            hh[j] = __float2bfloat16(h);
            hl[j] = __float2bfloat16(h - __bfloat162float(hh[j]));
        }
        *(float4*)(g_c1 + rowbase)     = make_float4(cv[0], cv[1], cv[2], cv[3]);
        *(float4*)(g_c1 + rowbase + 4) = make_float4(cv[4], cv[5], cv[6], cv[7]);
        *(uint4*)(g_h1hi[rd ^ 1] + rowbase) = *(const uint4*)hh;
        *(uint4*)(g_h1lo[rd ^ 1] + rowbase) = *(const uint4*)hl;
    }
}

// ---------------- phase B: layer-1 step (K=1024, two segments) ----------------
__global__ void __launch_bounds__(256) phaseB_k(int rd)
{
    extern __shared__ char sm[];
    uint32_t sb = smem_u32(sm);
    const int tid = threadIdx.x, lane = tid & 31, wid = tid >> 5;
    const int wm = wid >> 2, wn = wid & 3;
    const int b0 = blockIdx.x * MB, u0 = blockIdx.y * NU;

    const __nv_bfloat16* AHs[2] = { g_h1hi[rd ^ 1], g_h2hi[rd] };
    const __nv_bfloat16* ALs[2] = { g_h1lo[rd ^ 1], g_h2lo[rd] };
    const __nv_bfloat16* WHs[2] = { g_wih1hi, g_whh1hi };
    const __nv_bfloat16* WLs[2] = { g_wih1lo, g_whh1lo };

    stage_load(sb, AHs[0], ALs[0], WHs[0], WLs[0], b0, u0, 0, tid);
    CP_COMMIT();
    stage_load(sb + STAGE_BYTES, AHs[0], ALs[0], WHs[0], WLs[0], b0, u0, KC, tid);
    CP_COMMIT();

    float d[2][4][4] = {};
    run_pipeline<16>(sb, AHs, ALs, WHs, WLs, b0, u0, tid, d, wm, wn, lane);

    float* gbuf = (float*)sm;
    store_gbuf(gbuf, d, wm, wn, lane);
    __syncthreads();

    {
        int row = tid >> 2, ub = (tid & 3) * 8;
        size_t rowbase = (size_t)(b0 + row) * HD + u0 + ub;
        float4 ca = *(const float4*)(g_c2 + rowbase);
        float4 cb = *(const float4*)(g_c2 + rowbase + 4);
        float cv[8] = {ca.x, ca.y, ca.z, ca.w, cb.x, cb.y, cb.z, cb.w};
        float hv[8];
        __align__(16) __nv_bfloat16 hh[8], hl[8];
        #pragma unroll
        for (int j = 0; j < 8; j++) {
            int ul = ub + j;
            int ug = u0 + ul;
            float iv = gbuf[row * 132 + ul]      + g_b1[ug];
            float fv = gbuf[row * 132 + 32 + ul] + g_b1[HD + ug];
            float gv = gbuf[row * 132 + 64 + ul] + g_b1[2*HD + ug];
            float ov = gbuf[row * 132 + 96 + ul] + g_b1[3*HD + ug];
            float cn = sigf(fv) * cv[j] + sigf(iv) * tanhsf(gv);
            cv[j] = cn;
            float h = sigf(ov) * tanhsf(cn);
            hv[j] = h;
            hh[j] = __float2bfloat16(h);
            hl[j] = __float2bfloat16(h - __bfloat162float(hh[j]));
        }
        *(float4*)(g_c2 + rowbase)     = make_float4(cv[0], cv[1], cv[2], cv[3]);
        *(float4*)(g_c2 + rowbase + 4) = make_float4(cv[4], cv[5], cv[6], cv[7]);
        *(float4*)(g_h2f[rd ^ 1] + rowbase)     = make_float4(hv[0], hv[1], hv[2], hv[3]);
        *(float4*)(g_h2f[rd ^ 1] + rowbase + 4) = make_float4(hv[4], hv[5], hv[6], hv[7]);
        *(uint4*)(g_h2hi[rd ^ 1] + rowbase) = *(const uint4*)hh;
        *(uint4*)(g_h2lo[rd ^ 1] + rowbase) = *(const uint4*)hl;
    }
}

// ---------------- final prediction ----------------
__global__ void __launch_bounds__(256) final_y(
    int rd, const float* __restrict__ w_lin, const float* __restrict__ b_lin,
    float* __restrict__ out)
{
    int tid = threadIdx.x;
    int rrow = blockIdx.x * 128 + (tid >> 1);   // grid 4
    int p = tid & 1;
    const float4* hr = (const float4*)(g_h2f[rd] + (size_t)rrow * HD);
    const float4* wl = (const float4*)w_lin;
    float s = 0.f;
    #pragma unroll 16
    for (int kk = p; kk < HD / 4; kk += 2) {
        float4 a = hr[kk]; float4 w = wl[kk];
        s += a.x * w.x + a.y * w.y + a.z * w.z + a.w * w.w;
    }
    s += __shfl_xor_sync(0xffffffffu, s, 1);
    if (p == 0) out[(size_t)rrow * TD + (TD - 1)] = s + b_lin[0];
}

// ---------------- host launcher ----------------
extern "C" void kernel_launch(void* const* d_in, const int* in_sizes, int n_in,
                              void* d_out, int out_size)
{
    const float* x     = (const float*)d_in[0];
    const float* w_ih0 = (const float*)d_in[3];
    const float* w_hh0 = (const float*)d_in[4];
    const float* b_ih0 = (const float*)d_in[5];
    const float* b_hh0 = (const float*)d_in[6];
    const float* w_ih1 = (const float*)d_in[7];
    const float* w_hh1 = (const float*)d_in[8];
    const float* b_ih1 = (const float*)d_in[9];
    const float* b_hh1 = (const float*)d_in[10];
    const float* w_lin = (const float*)d_in[11];
    const float* b_lin = (const float*)d_in[12];
    float* out = (float*)d_out;

    cudaFuncSetAttribute(phaseA_k, cudaFuncAttributeMaxDynamicSharedMemorySize, SMEM_TOTAL);
    cudaFuncSetAttribute(phaseB_k, cudaFuncAttributeMaxDynamicSharedMemorySize, SMEM_TOTAL);

    zero_state<<<1024, 256>>>();
    prep_bias<<<8, 256>>>(b_ih0, b_hh0, b_ih1, b_hh1);
    splitw<<<4096, 256>>>(w_hh0, 0);
    splitw<<<4096, 256>>>(w_ih1, 1);
    splitw<<<4096, 256>>>(w_hh1, 2);

    dim3 grid(BD / MB, HD / NU);   // (8, 16) = 128 CTAs
    int s = 0;
    for (int t = 0; t < TD; ++t, ++s) {
        phaseA_k<<<grid, 256, SMEM_TOTAL>>>(s & 1, x, t, 0,
                                            nullptr, nullptr, nullptr, 0, w_ih0);
        phaseB_k<<<grid, 256, SMEM_TOTAL>>>(s & 1);
    }
    for (int i = 1; i < TD; ++i, ++s) {
        phaseA_k<<<grid, 256, SMEM_TOTAL>>>(s & 1, nullptr, 0, (i == 1) ? 1 : 0,
                                            w_lin, b_lin, out, i - 1, w_ih0);
        phaseB_k<<<grid, 256, SMEM_TOTAL>>>(s & 1);
    }
    final_y<<<4, 256>>>(s & 1, w_lin, b_lin, out);
}

// round 12
// speedup vs baseline: 2.5495x; 1.2245x over previous
#include <cuda_runtime.h>
#include <cuda_fp16.h>
#include <stdint.h>
#include <math.h>

// ---------------- dims ----------------
#define HD 512
#define BD 512
#define TD 128

#define MB 64        // batch rows per CTA (M)
#define NU 32        // units per CTA; N = 4 gates x 32 = 128
#define KC 64        // k per stage

// smem stage layout: rows padded to 144B (64 fp16 = 128B data + 16B pad)
#define ROWB 144
#define A_BYTES (64 * ROWB)                 // 9216
#define W_BYTES (128 * ROWB)                // 18432
#define OFF_WHI A_BYTES
#define OFF_WLO (A_BYTES + W_BYTES)
#define STAGE_BYTES (A_BYTES + 2 * W_BYTES) // 46080
#define NSTG 4
#define OFF_XS (NSTG * STAGE_BYTES)         // 184320
#define SMEM_TOTAL (OFF_XS + 1024)          // 185344

// ---------------- persistent device state ----------------
__device__ float g_c1[BD*HD];
__device__ float g_c2[BD*HD];
__device__ float g_h2f[2][BD*HD];
__device__ __align__(16) __half g_h1q[2][BD*HD];
__device__ __align__(16) __half g_h2q[2][BD*HD];
__device__ float g_b0[4*HD], g_b1[4*HD];
__device__ __align__(16) __half g_whh0a[4*HD*HD], g_whh0b[4*HD*HD];
__device__ __align__(16) __half g_wih1a[4*HD*HD], g_wih1b[4*HD*HD];
__device__ __align__(16) __half g_whh1a[4*HD*HD], g_whh1b[4*HD*HD];

// ---------------- helpers ----------------
__device__ __forceinline__ uint32_t smem_u32(const void* p) {
    uint32_t a;
    asm("{ .reg .u64 t; cvta.to.shared.u64 t, %1; cvt.u32.u64 %0, t; }" : "=r"(a) : "l"(p));
    return a;
}
__device__ __forceinline__ void cpa16(uint32_t dst, const void* src) {
    asm volatile("cp.async.cg.shared.global [%0], [%1], 16;" :: "r"(dst), "l"(src));
}
#define CP_COMMIT() asm volatile("cp.async.commit_group;")
#define CP_WAIT(n)  asm volatile("cp.async.wait_group %0;" :: "n"(n))

__device__ __forceinline__ void ldm4(uint32_t (&r)[4], uint32_t addr) {
    asm volatile("ldmatrix.sync.aligned.m8n8.x4.shared.b16 {%0,%1,%2,%3}, [%4];"
        : "=r"(r[0]), "=r"(r[1]), "=r"(r[2]), "=r"(r[3]) : "r"(addr));
}
__device__ __forceinline__ void mma_f16(float (&d)[4], const uint32_t a[4], const uint32_t b[2]) {
    asm volatile("mma.sync.aligned.m16n8k16.row.col.f32.f16.f16.f32 "
        "{%0,%1,%2,%3}, {%4,%5,%6,%7}, {%8,%9}, {%0,%1,%2,%3};"
        : "+f"(d[0]), "+f"(d[1]), "+f"(d[2]), "+f"(d[3])
        : "r"(a[0]), "r"(a[1]), "r"(a[2]), "r"(a[3]), "r"(b[0]), "r"(b[1]));
}

__device__ __forceinline__ float sigf(float z) { return 1.0f / (1.0f + __expf(-z)); }
__device__ __forceinline__ float tanhsf(float z) {
    float e = __expf(2.0f * z);
    return 1.0f - 2.0f / (e + 1.0f);
}

// ---------------- stage loader: A 64xKC fp16, W(hi,lo) 128xKC fp16 ----------------
__device__ __forceinline__ void stage_load(uint32_t st,
    const __half* __restrict__ a,
    const __half* __restrict__ whi, const __half* __restrict__ wlo,
    int b0, int u0, int k0, int tid)
{
    #pragma unroll
    for (int q = 0; q < 2; q++) {
        int i = tid + q * 256;
        int r = i >> 3, s = (i & 7) * 8;           // s in fp16 elems (16B chunks)
        uint32_t doff = (uint32_t)(r * ROWB + s * 2);
        size_t goff = (size_t)(b0 + r) * HD + k0 + s;
        cpa16(st + doff, a + goff);
    }
    #pragma unroll
    for (int q = 0; q < 4; q++) {
        int i = tid + q * 256;
        int n = i >> 3, s = (i & 7) * 8;
        int wrow = ((n >> 5) << 9) + u0 + (n & 31);  // gate*512 + u
        uint32_t doff = (uint32_t)(n * ROWB + s * 2);
        size_t goff = (size_t)wrow * HD + k0 + s;
        cpa16(st + OFF_WHI + doff, whi + goff);
        cpa16(st + OFF_WLO + doff, wlo + goff);
    }
}

// ---------------- compute one 64-k stage: 2 products into d ----------------
__device__ __forceinline__ void compute_stage(uint32_t sbase, float (&d)[2][4][4],
                                              int wm, int wn, int lane)
{
    const int l7 = lane & 7, grp = lane >> 3;
    const uint32_t a_row = (uint32_t)(((grp & 1) << 3) + l7);
    const uint32_t a_kb  = (uint32_t)((grp >> 1) << 4);
    const uint32_t b_n   = (uint32_t)(((grp >> 1) << 3) + l7);
    const uint32_t b_kb  = (uint32_t)((grp & 1) << 4);

    #pragma unroll
    for (int kk = 0; kk < 4; kk++) {
        uint32_t kb = kk * 32;   // bytes: k16 step = 32B
        uint32_t Ah[2][4], Bh[2][4], Bl[2][4];
        #pragma unroll
        for (int mi = 0; mi < 2; mi++) {
            uint32_t ra = sbase + (wm * 32 + mi * 16 + a_row) * ROWB + kb + a_kb;
            ldm4(Ah[mi], ra);
        }
        #pragma unroll
        for (int p = 0; p < 2; p++) {
            uint32_t rb = sbase + OFF_WHI + (wn * 32 + p * 16 + b_n) * ROWB + kb + b_kb;
            ldm4(Bh[p], rb);
            ldm4(Bl[p], rb + W_BYTES);
        }
        #pragma unroll
        for (int mi = 0; mi < 2; mi++) {
            #pragma unroll
            for (int ni = 0; ni < 4; ni++) {
                const uint32_t* bh = &Bh[ni >> 1][(ni & 1) * 2];
                const uint32_t* bl = &Bl[ni >> 1][(ni & 1) * 2];
                mma_f16(d[mi][ni], Ah[mi], bh);
                mma_f16(d[mi][ni], Ah[mi], bl);
            }
        }
    }
}

// ---------------- accum -> smem gate buffer ----------------
__device__ __forceinline__ void store_gbuf(float* gbuf, float (&d)[2][4][4],
                                           int wm, int wn, int lane)
{
    const int gid = lane >> 2, tig = lane & 3;
    #pragma unroll
    for (int mi = 0; mi < 2; mi++) {
        #pragma unroll
        for (int ni = 0; ni < 4; ni++) {
            int row = wm * 32 + mi * 16 + gid;
            int c0 = wn * 32 + ni * 8 + tig * 2;
            gbuf[row * 132 + c0]           = d[mi][ni][0];
            gbuf[row * 132 + c0 + 1]       = d[mi][ni][1];
            gbuf[(row + 8) * 132 + c0]     = d[mi][ni][2];
            gbuf[(row + 8) * 132 + c0 + 1] = d[mi][ni][3];
        }
    }
}

// ---------------- 4-stage ring pipeline, one sync per stage ----------------
template<int NS>
__device__ __forceinline__ void run_pipeline(
    uint32_t sb,
    const __half* const* As,
    const __half* const* WHs, const __half* const* WLs,
    int b0, int u0, int tid,
    float (&d)[2][4][4], int wm, int wn, int lane)
{
    // stages 0,1 already preloaded by caller
    #pragma unroll 1
    for (int i = 0; i < NS; i++) {
        if (i + 2 < NS) {
            int j = i + 2, sg = j >> 3;
            stage_load(sb + (j % NSTG) * STAGE_BYTES, As[sg], WHs[sg], WLs[sg],
                       b0, u0, (j & 7) * KC, tid);
            CP_COMMIT();
            CP_WAIT(2);
        } else {
            CP_WAIT(0);
        }
        __syncthreads();
        compute_stage(sb + (i % NSTG) * STAGE_BYTES, d, wm, wn, lane);
    }
    __syncthreads();   // protect gbuf aliasing of stage slots
}

// ---------------- setup kernels ----------------
__global__ void __launch_bounds__(256) zero_state() {
    int idx = blockIdx.x * 256 + threadIdx.x;   // grid 1024
    g_c1[idx] = 0.f; g_c2[idx] = 0.f;
    __half z = __float2half(0.f);
    g_h1q[0][idx] = z; g_h2q[0][idx] = z;
}
__global__ void __launch_bounds__(256) prep_bias(
    const float* __restrict__ b_ih0, const float* __restrict__ b_hh0,
    const float* __restrict__ b_ih1, const float* __restrict__ b_hh1) {
    int j = blockIdx.x * 256 + threadIdx.x;     // grid 8
    g_b0[j] = b_ih0[j] + b_hh0[j];
    g_b1[j] = b_ih1[j] + b_hh1[j];
}
// w = w1(fp16) + w2(fp16, residual; may be subnormal)
__global__ void __launch_bounds__(256) splitw(const float* __restrict__ w, int which) {
    __half *hi, *lo;
    if (which == 0)      { hi = g_whh0a; lo = g_whh0b; }
    else if (which == 1) { hi = g_wih1a; lo = g_wih1b; }
    else                 { hi = g_whh1a; lo = g_whh1b; }
    int i = blockIdx.x * 256 + threadIdx.x;     // grid 4096
    float v = w[i];
    __half h = __float2half_rn(v);
    hi[i] = h;
    lo[i] = __float2half_rn(v - __half2float(h));
}

// ---------------- phase A: layer-0 step ----------------
__global__ void __launch_bounds__(256) phaseA_k(
    int rd, const float* __restrict__ xin, int t, int y_from_c2,
    const float* __restrict__ w_lin, const float* __restrict__ b_lin,
    float* __restrict__ out, int t_out, const float* __restrict__ w_ih0)
{
    extern __shared__ char sm[];
    uint32_t sb = smem_u32(sm);
    const int tid = threadIdx.x, lane = tid & 31, wid = tid >> 5;
    const int wm = wid >> 2, wn = wid & 3;
    const int b0 = blockIdx.x * MB, u0 = blockIdx.y * NU;
    float* xs = (float*)(sm + OFF_XS);

    const __half* As[2]  = { g_h1q[rd], g_h1q[rd] };
    const __half* WHs[2] = { g_whh0a, g_whh0a };
    const __half* WLs[2] = { g_whh0b, g_whh0b };

    // kick off pipeline fill FIRST so y/x work overlaps the loads
    stage_load(sb, As[0], WHs[0], WLs[0], b0, u0, 0, tid);
    CP_COMMIT();
    stage_load(sb + STAGE_BYTES, As[0], WHs[0], WLs[0], b0, u0, KC, tid);
    CP_COMMIT();

    // input scalar per batch row (teacher-forced or autoregressive)
    if (xin != nullptr) {
        if (tid < MB) xs[tid] = xin[(size_t)(b0 + tid) * TD + t];
    } else {
        const float* ysrc = y_from_c2 ? g_c2 : g_h2f[rd];
        int rrow = tid >> 2, p = tid & 3;
        const float4* hr = (const float4*)(ysrc + (size_t)(b0 + rrow) * HD);
        const float4* wl = (const float4*)w_lin;
        float s = 0.f;
        #pragma unroll 8
        for (int kk = p; kk < HD / 4; kk += 4) {
            float4 a = hr[kk]; float4 w = wl[kk];
            s += a.x * w.x + a.y * w.y + a.z * w.z + a.w * w.w;
        }
        s += __shfl_xor_sync(0xffffffffu, s, 1);
        s += __shfl_xor_sync(0xffffffffu, s, 2);
        if (p == 0) {
            float yv = s + b_lin[0];
            xs[rrow] = yv;
            if (blockIdx.y == 0) out[(size_t)(b0 + rrow) * TD + t_out] = yv;
        }
    }

    float d[2][4][4] = {};
    run_pipeline<8>(sb, As, WHs, WLs, b0, u0, tid, d, wm, wn, lane);

    float* gbuf = (float*)sm;
    store_gbuf(gbuf, d, wm, wn, lane);
    __syncthreads();

    // cell update: thread -> (row, 8 consecutive u)
    {
        int row = tid >> 2, ub = (tid & 3) * 8;
        float xi = xs[row];
        size_t rowbase = (size_t)(b0 + row) * HD + u0 + ub;
        float4 ca = *(const float4*)(g_c1 + rowbase);
        float4 cb = *(const float4*)(g_c1 + rowbase + 4);
        float cv[8] = {ca.x, ca.y, ca.z, ca.w, cb.x, cb.y, cb.z, cb.w};
        __align__(16) __half hq[8];
        #pragma unroll
        for (int j = 0; j < 8; j++) {
            int ul = ub + j;
            int ug = u0 + ul;
            float iv = gbuf[row * 132 + ul]       + g_b0[ug]          + xi * w_ih0[ug];
            float fv = gbuf[row * 132 + 32 + ul]  + g_b0[HD + ug]     + xi * w_ih0[HD + ug];
            float gv = gbuf[row * 132 + 64 + ul]  + g_b0[2*HD + ug]   + xi * w_ih0[2*HD + ug];
            float ov = gbuf[row * 132 + 96 + ul]  + g_b0[3*HD + ug]   + xi * w_ih0[3*HD + ug];
            float cn = sigf(fv) * cv[j] + sigf(iv) * tanhsf(gv);
            cv[j] = cn;
            float h = sigf(ov) * tanhsf(cn);
            hq[j] = __float2half_rn(h);
        }
        *(float4*)(g_c1 + rowbase)     = make_float4(cv[0], cv[1], cv[2], cv[3]);
        *(float4*)(g_c1 + rowbase + 4) = make_float4(cv[4], cv[5], cv[6], cv[7]);
        *(uint4*)(g_h1q[rd ^ 1] + rowbase) = *(const uint4*)hq;
    }
}

// ---------------- phase B: layer-1 step (K=1024, two segments) ----------------
__global__ void __launch_bounds__(256) phaseB_k(int rd)
{
    extern __shared__ char sm[];
    uint32_t sb = smem_u32(sm);
    const int tid = threadIdx.x, lane = tid & 31, wid = tid >> 5;
    const int wm = wid >> 2, wn = wid & 3;
    const int b0 = blockIdx.x * MB, u0 = blockIdx.y * NU;

    const __half* As[2]  = { g_h1q[rd ^ 1], g_h2q[rd] };
    const __half* WHs[2] = { g_wih1a, g_whh1a };
    const __half* WLs[2] = { g_wih1b, g_whh1b };

    stage_load(sb, As[0], WHs[0], WLs[0], b0, u0, 0, tid);
    CP_COMMIT();
    stage_load(sb + STAGE_BYTES, As[0], WHs[0], WLs[0], b0, u0, KC, tid);
    CP_COMMIT();

    float d[2][4][4] = {};
    run_pipeline<16>(sb, As, WHs, WLs, b0, u0, tid, d, wm, wn, lane);

    float* gbuf = (float*)sm;
    store_gbuf(gbuf, d, wm, wn, lane);
    __syncthreads();

    {
        int row = tid >> 2, ub = (tid & 3) * 8;
        size_t rowbase = (size_t)(b0 + row) * HD + u0 + ub;
        float4 ca = *(const float4*)(g_c2 + rowbase);
        float4 cb = *(const float4*)(g_c2 + rowbase + 4);
        float cv[8] = {ca.x, ca.y, ca.z, ca.w, cb.x, cb.y, cb.z, cb.w};
        float hv[8];
        __align__(16) __half hq[8];
        #pragma unroll
        for (int j = 0; j < 8; j++) {
            int ul = ub + j;
            int ug = u0 + ul;
            float iv = gbuf[row * 132 + ul]      + g_b1[ug];
            float fv = gbuf[row * 132 + 32 + ul] + g_b1[HD + ug];
            float gv = gbuf[row * 132 + 64 + ul] + g_b1[2*HD + ug];
            float ov = gbuf[row * 132 + 96 + ul] + g_b1[3*HD + ug];
            float cn = sigf(fv) * cv[j] + sigf(iv) * tanhsf(gv);
            cv[j] = cn;
            float h = sigf(ov) * tanhsf(cn);
            hv[j] = h;
            hq[j] = __float2half_rn(h);
        }
        *(float4*)(g_c2 + rowbase)     = make_float4(cv[0], cv[1], cv[2], cv[3]);
        *(float4*)(g_c2 + rowbase + 4) = make_float4(cv[4], cv[5], cv[6], cv[7]);
        *(float4*)(g_h2f[rd ^ 1] + rowbase)     = make_float4(hv[0], hv[1], hv[2], hv[3]);
        *(float4*)(g_h2f[rd ^ 1] + rowbase + 4) = make_float4(hv[4], hv[5], hv[6], hv[7]);
        *(uint4*)(g_h2q[rd ^ 1] + rowbase) = *(const uint4*)hq;
    }
}

// ---------------- final prediction ----------------
__global__ void __launch_bounds__(256) final_y(
    int rd, const float* __restrict__ w_lin, const float* __restrict__ b_lin,
    float* __restrict__ out)
{
    int tid = threadIdx.x;
    int rrow = blockIdx.x * 128 + (tid >> 1);   // grid 4
    int p = tid & 1;
    const float4* hr = (const float4*)(g_h2f[rd] + (size_t)rrow * HD);
    const float4* wl = (const float4*)w_lin;
    float s = 0.f;
    #pragma unroll 16
    for (int kk = p; kk < HD / 4; kk += 2) {
        float4 a = hr[kk]; float4 w = wl[kk];
        s += a.x * w.x + a.y * w.y + a.z * w.z + a.w * w.w;
    }
    s += __shfl_xor_sync(0xffffffffu, s, 1);
    if (p == 0) out[(size_t)rrow * TD + (TD - 1)] = s + b_lin[0];
}

// ---------------- host launcher ----------------
extern "C" void kernel_launch(void* const* d_in, const int* in_sizes, int n_in,
                              void* d_out, int out_size)
{
    const float* x     = (const float*)d_in[0];
    const float* w_ih0 = (const float*)d_in[3];
    const float* w_hh0 = (const float*)d_in[4];
    const float* b_ih0 = (const float*)d_in[5];
    const float* b_hh0 = (const float*)d_in[6];
    const float* w_ih1 = (const float*)d_in[7];
    const float* w_hh1 = (const float*)d_in[8];
    const float* b_ih1 = (const float*)d_in[9];
    const float* b_hh1 = (const float*)d_in[10];
    const float* w_lin = (const float*)d_in[11];
    const float* b_lin = (const float*)d_in[12];
    float* out = (float*)d_out;

    cudaFuncSetAttribute(phaseA_k, cudaFuncAttributeMaxDynamicSharedMemorySize, SMEM_TOTAL);
    cudaFuncSetAttribute(phaseB_k, cudaFuncAttributeMaxDynamicSharedMemorySize, SMEM_TOTAL);

    zero_state<<<1024, 256>>>();
    prep_bias<<<8, 256>>>(b_ih0, b_hh0, b_ih1, b_hh1);
    splitw<<<4096, 256>>>(w_hh0, 0);
    splitw<<<4096, 256>>>(w_ih1, 1);
    splitw<<<4096, 256>>>(w_hh1, 2);

    dim3 grid(BD / MB, HD / NU);   // (8, 16) = 128 CTAs
    int s = 0;
    for (int t = 0; t < TD; ++t, ++s) {
        phaseA_k<<<grid, 256, SMEM_TOTAL>>>(s & 1, x, t, 0,
                                            nullptr, nullptr, nullptr, 0, w_ih0);
        phaseB_k<<<grid, 256, SMEM_TOTAL>>>(s & 1);
    }
    for (int i = 1; i < TD; ++i, ++s) {
        phaseA_k<<<grid, 256, SMEM_TOTAL>>>(s & 1, nullptr, 0, (i == 1) ? 1 : 0,
                                            w_lin, b_lin, out, i - 1, w_ih0);
        phaseB_k<<<grid, 256, SMEM_TOTAL>>>(s & 1);
    }
    final_y<<<4, 256>>>(s & 1, w_lin, b_lin, out);
}